// round 2
// baseline (speedup 1.0000x reference)
#include <cuda_runtime.h>
#include <cuda_bf16.h>

// Problem constants
#define NNODE   16384
#define CDIM    48
#define KNN     9
#define BATCHSZ 4096

typedef unsigned long long u64;

// -------- scratch (device globals; no allocation allowed) --------
__device__ __align__(256) float g_xf[NNODE * CDIM];   // [N,48] node features
__device__ float g_sq[NNODE];                         // row squared norms
__device__ int   g_nbr[NNODE * KNN];                  // knn indices
__device__ int   g_deg[NNODE];                        // degree over src

// packed fp32x2 fma (sm_100+/sm_103a): 2 IEEE fp32 FMAs per instruction
__device__ __forceinline__ u64 fma2(u64 a, u64 b, u64 c) {
    u64 d;
    asm("fma.rn.f32x2 %0, %1, %2, %3;" : "=l"(d) : "l"(a), "l"(b), "l"(c));
    return d;
}
__device__ __forceinline__ void unpack2(u64 v, float& lo, float& hi) {
    asm("mov.b64 {%0, %1}, %2;" : "=f"(lo), "=f"(hi) : "l"(v));
}

// ============ kernel 1: [B,C,H,W] -> [N,C] transpose ============
__global__ __launch_bounds__(192) void transpose_kernel(const float* __restrict__ x) {
    int bh = blockIdx.x;            // b*64 + h, 256 blocks
    __shared__ float s[48][65];
    const float* src = x + (size_t)(bh >> 6) * 48 * 4096 + (bh & 63) * 64;
    for (int idx = threadIdx.x; idx < 48 * 64; idx += 192) {
        int c = idx >> 6, w = idx & 63;
        s[c][w] = src[c * 4096 + w];
    }
    __syncthreads();
    float* dst = g_xf + (size_t)bh * 64 * 48;
    for (int idx = threadIdx.x; idx < 48 * 64; idx += 192) {
        int w = idx / 48, c = idx - w * 48;
        dst[w * 48 + c] = s[c][w];
    }
}

// ============ kernel 2: row norms + zero deg ============
__global__ __launch_bounds__(256) void sq_kernel() {
    int i = blockIdx.x * 256 + threadIdx.x;   // 64 blocks
    if (i >= NNODE) return;
    const float4* r = (const float4*)(g_xf + (size_t)i * CDIM);
    float s = 0.f;
#pragma unroll
    for (int k = 0; k < 12; k++) {
        float4 v = r[k];
        s += v.x * v.x + v.y * v.y + v.z * v.z + v.w * v.w;
    }
    g_sq[i] = s;
    g_deg[i] = 0;
}

// ============ kernel 3: knn (top-9 smallest dist, lower-index ties) ============
// 256 blocks x 256 threads. Block owns 64 centers; 4 threads per center split
// the candidate sweep (interleaved rows within each 128-row smem tile).
__global__ __launch_bounds__(256) void knn_kernel() {
    __shared__ __align__(16) float stile[128 * 48];   // 24KB candidate tile
    __shared__ float ssq[128];
    __shared__ float smd[64 * 4 * KNN];               // partial dists
    __shared__ int   smi[64 * 4 * KNN];               // partial idxs

    const int tid  = threadIdx.x;
    const int il   = tid & 63;
    const int part = tid >> 6;
    const int i    = blockIdx.x * 64 + il;
    const int batch  = blockIdx.x >> 6;
    const int jbase  = batch << 12;
    const int jcount = (batch == 3) ? (BATCHSZ - 1) : BATCHSZ;  // exclude node 16383

    // center features in registers (as fp32x2 pairs)
    u64 xi2[24];
    {
        const ulonglong2* xr = (const ulonglong2*)(g_xf + (size_t)i * CDIM);
#pragma unroll
        for (int c = 0; c < 12; c++) {
            ulonglong2 v = xr[c];
            xi2[2 * c] = v.x; xi2[2 * c + 1] = v.y;
        }
    }
    const float sqi = g_sq[i];

    float d9[KNN]; int n9[KNN];
#pragma unroll
    for (int k = 0; k < KNN; k++) { d9[k] = 3.402823466e+38f; n9[k] = 0x7fffffff; }

    for (int jt = 0; jt < jcount; jt += 128) {
        const int rem = min(128, jcount - jt);
        // cooperative tile load (float4, layouts match: contiguous rows)
        {
            const int nf4 = rem * 12;
            const float4* src = (const float4*)(g_xf + (size_t)(jbase + jt) * CDIM);
            float4* dst = (float4*)stile;
            for (int f = tid; f < nf4; f += 256) dst[f] = src[f];
            if (tid < rem) ssq[tid] = g_sq[jbase + jt + tid];
        }
        __syncthreads();

        for (int r = part; r < rem; r += 4) {
            const ulonglong2* xj = (const ulonglong2*)(stile + r * 48);
            u64 a0 = 0, a1 = 0, a2 = 0, a3 = 0;
#pragma unroll
            for (int c = 0; c < 12; c += 2) {
                ulonglong2 v0 = xj[c];
                ulonglong2 v1 = xj[c + 1];
                a0 = fma2(xi2[2 * c],     v0.x, a0);
                a1 = fma2(xi2[2 * c + 1], v0.y, a1);
                a2 = fma2(xi2[2 * c + 2], v1.x, a2);
                a3 = fma2(xi2[2 * c + 3], v1.y, a3);
            }
            float l0, h0, l1, h1, l2, h2, l3, h3;
            unpack2(a0, l0, h0); unpack2(a1, l1, h1);
            unpack2(a2, l2, h2); unpack2(a3, l3, h3);
            float dot = ((l0 + h0) + (l1 + h1)) + ((l2 + h2) + (l3 + h3));
            float dist = (sqi + ssq[r]) - 2.0f * dot;

            if (dist < d9[8]) {   // strict < : ascending j keeps lowest index on ties
                d9[8] = dist; n9[8] = jbase + jt + r;
#pragma unroll
                for (int k = 8; k > 0; k--) {
                    if (d9[k] < d9[k - 1]) {
                        float td = d9[k]; d9[k] = d9[k - 1]; d9[k - 1] = td;
                        int   ti = n9[k]; n9[k] = n9[k - 1]; n9[k - 1] = ti;
                    }
                }
            }
        }
        __syncthreads();
    }

    // publish partials
    {
        const int base = (il * 4 + part) * KNN;
#pragma unroll
        for (int k = 0; k < KNN; k++) { smd[base + k] = d9[k]; smi[base + k] = n9[k]; }
    }
    __syncthreads();

    // 4-way lexicographic merge by (dist, idx), done by part-0 threads
    if (part == 0) {
        if (i == NNODE - 1) {
            // node 16383: alone in batch 4 -> self + 8 lowest-index -inf ties (0..7)
            g_nbr[i * KNN + 0] = NNODE - 1;
#pragma unroll
            for (int k = 1; k < KNN; k++) g_nbr[i * KNN + k] = k - 1;
        } else {
            int p[4] = {0, 0, 0, 0};
            for (int k = 0; k < KNN; k++) {
                float bd = 3.402823466e+38f; int bi = 0x7fffffff; int bq = 0;
#pragma unroll
                for (int q = 0; q < 4; q++) {
                    const int pq = p[q];
                    float dq = 3.402823466e+38f; int iq = 0x7fffffff;
                    if (pq < KNN) {
                        dq = smd[(il * 4 + q) * KNN + pq];
                        iq = smi[(il * 4 + q) * KNN + pq];
                    }
                    if (dq < bd || (dq == bd && iq < bi)) { bd = dq; bi = iq; bq = q; }
                }
                p[bq]++;
                g_nbr[i * KNN + k] = bi;
            }
        }
    }
}

// ============ kernel 4: degree over src ============
__global__ __launch_bounds__(256) void deg_kernel() {
    int e = blockIdx.x * 256 + threadIdx.x;
    if (e < NNODE * KNN) atomicAdd(&g_deg[g_nbr[e]], 1);
}

// ============ kernel 5: fused gather + (xf@W0 + tx1@W1 + b) + relu ============
// block = 384 threads = 8 rows x 48 output cols
__global__ __launch_bounds__(384) void out_kernel(const float* __restrict__ W0,
                                                  const float* __restrict__ W1,
                                                  const float* __restrict__ b,
                                                  float* __restrict__ out) {
    __shared__ float W0s[2304], W1s[2304], bs[48];
    __shared__ float sx[8][48], sg[8][48], sdin[8];
    const int tid = threadIdx.x;
    for (int k = tid; k < 2304; k += 384) { W0s[k] = W0[k]; W1s[k] = W1[k]; }
    if (tid < 48) bs[tid] = b[tid];

    const int row = tid / 48, o = tid % 48;
    const int i = blockIdx.x * 8 + row;

    sx[row][o] = g_xf[(size_t)i * 48 + o];
    float g = 0.f;
    const int* nb = &g_nbr[i * KNN];
#pragma unroll
    for (int k = 0; k < KNN; k++) {
        const int j = nb[k];
        const float dj = rsqrtf((float)g_deg[j]);
        g += dj * g_xf[(size_t)j * 48 + o];
    }
    sg[row][o] = g;
    if (o == 0) sdin[row] = rsqrtf((float)g_deg[i]);
    __syncthreads();

    float a0 = 0.f, a1 = 0.f;
#pragma unroll
    for (int c = 0; c < 48; c++) {
        a0 += sx[row][c] * W0s[c * 48 + o];
        a1 += sg[row][c] * W1s[c * 48 + o];
    }
    const float v = bs[o] + a0 - sdin[row] * a1;
    out[(size_t)i * 48 + o] = fmaxf(v, 0.f);
}

// ============ launch ============
extern "C" void kernel_launch(void* const* d_in, const int* in_sizes, int n_in,
                              void* d_out, int out_size) {
    const float* x  = (const float*)d_in[0];
    const float* W0 = (const float*)d_in[1];
    const float* W1 = (const float*)d_in[2];
    const float* b  = (const float*)d_in[3];
    float* out = (float*)d_out;

    transpose_kernel<<<256, 192>>>(x);
    sq_kernel<<<64, 256>>>();
    knn_kernel<<<256, 256>>>();
    deg_kernel<<<(NNODE * KNN + 255) / 256, 256>>>();
    out_kernel<<<NNODE / 8, 384>>>(W0, W1, b, out);
}

// round 4
// speedup vs baseline: 1.1963x; 1.1963x over previous
#include <cuda_runtime.h>
#include <cuda_bf16.h>

// Problem constants
#define NNODE   16384
#define CDIM    48
#define KNN     9
#define BATCHSZ 4096
#define TILE    64

typedef unsigned long long u64;

// -------- scratch (device globals; no allocation allowed) --------
__device__ __align__(256) float g_xf[NNODE * CDIM];   // [N,48] node features
__device__ float g_sq[NNODE];                         // row squared norms
__device__ int   g_nbr[NNODE * KNN];                  // knn indices
__device__ int   g_deg[NNODE];                        // degree over src

// packed fp32x2 ops (sm_103a): 2 IEEE fp32 ops per instruction
__device__ __forceinline__ u64 fma2(u64 a, u64 b, u64 c) {
    u64 d;
    asm("fma.rn.f32x2 %0, %1, %2, %3;" : "=l"(d) : "l"(a), "l"(b), "l"(c));
    return d;
}
__device__ __forceinline__ u64 add2(u64 a, u64 b) {
    u64 d;
    asm("add.rn.f32x2 %0, %1, %2;" : "=l"(d) : "l"(a), "l"(b));
    return d;
}
__device__ __forceinline__ void unpack2(u64 v, float& lo, float& hi) {
    asm("mov.b64 {%0, %1}, %2;" : "=f"(lo), "=f"(hi) : "l"(v));
}

// ============ kernel 1: [B,C,H,W] -> [N,C] transpose + row norms + deg=0 ============
__global__ __launch_bounds__(192) void transpose_kernel(const float* __restrict__ x) {
    int bh = blockIdx.x;            // b*64 + h, 256 blocks
    __shared__ float s[48][65];
    const float* src = x + (size_t)(bh >> 6) * 48 * 4096 + (bh & 63) * 64;
    for (int idx = threadIdx.x; idx < 48 * 64; idx += 192) {
        int c = idx >> 6, w = idx & 63;
        s[c][w] = src[c * 4096 + w];
    }
    __syncthreads();
    float* dst = g_xf + (size_t)bh * 64 * 48;
    for (int idx = threadIdx.x; idx < 48 * 64; idx += 192) {
        int w = idx / 48, c = idx - w * 48;
        dst[w * 48 + c] = s[c][w];
    }
    if (threadIdx.x < 64) {
        int w = threadIdx.x;
        float acc = 0.f;
#pragma unroll
        for (int c = 0; c < 48; c++) acc += s[c][w] * s[c][w];
        g_sq[bh * 64 + w] = acc;
        g_deg[bh * 64 + w] = 0;
    }
}

// ============ kernel 2: knn (top-9 smallest dist, lower-index ties) ============
// 256 blocks x 256 threads, 2 blocks/SM. Block owns 64 centers; 4 threads per
// center split the candidate sweep. Candidate tiles of 64 rows staged in smem
// with register prefetch of the next tile. Centers live in registers as f32x2.
__global__ __launch_bounds__(256, 2) void knn_kernel() {
    __shared__ __align__(16) float stile[TILE * 48];   // 12.3KB candidate tile
    __shared__ float ssq[TILE];
    __shared__ float smd[64 * 4 * KNN];                // partial dists (merge)
    __shared__ int   smi[64 * 4 * KNN];                // partial idxs  (merge)

    const int tid  = threadIdx.x;
    const int il   = tid & 63;
    const int part = tid >> 6;
    const int i    = blockIdx.x * 64 + il;
    const int batch  = blockIdx.x >> 6;
    const int jbase  = batch << 12;
    const int jcount = (batch == 3) ? (BATCHSZ - 1) : BATCHSZ;  // exclude node 16383

    // center features in registers (as fp32x2 pairs)
    u64 xi2[24];
    {
        const ulonglong2* xr = (const ulonglong2*)(g_xf + (size_t)i * CDIM);
#pragma unroll
        for (int c = 0; c < 12; c++) {
            ulonglong2 v = xr[c];
            xi2[2 * c] = v.x; xi2[2 * c + 1] = v.y;
        }
    }
    const float sqi = g_sq[i];
    const float INF = __int_as_float(0x7f800000);

    float d9[KNN]; int n9[KNN];
#pragma unroll
    for (int k = 0; k < KNN; k++) { d9[k] = 3.402823466e+38f; n9[k] = 0x7fffffff; }

    const float4* gsrc = (const float4*)(g_xf + (size_t)jbase * CDIM);

    // prefetch registers
    float4 pf0, pf1, pf2; float pfs = 0.f;
    const float4 z4 = make_float4(0.f, 0.f, 0.f, 0.f);

    // preload tile 0
    {
        int rem0 = min(TILE, jcount);
        int lim = rem0 * 12;
        pf0 = (tid       < lim) ? gsrc[tid]       : z4;
        pf1 = (tid + 256 < lim) ? gsrc[tid + 256] : z4;
        pf2 = (tid + 512 < lim) ? gsrc[tid + 512] : z4;
        if (tid < TILE) pfs = (tid < rem0) ? g_sq[jbase + tid] : INF;
    }

    const int ntiles = BATCHSZ / TILE;  // 64
    for (int t = 0; t < ntiles; t++) {
        const int jt = t * TILE;
        __syncthreads();   // previous tile fully consumed
        {
            float4* dst = (float4*)stile;
            dst[tid] = pf0; dst[tid + 256] = pf1; dst[tid + 512] = pf2;
            if (tid < TILE) ssq[tid] = pfs;
        }
        __syncthreads();

        // prefetch next tile while computing on this one
        if (t + 1 < ntiles) {
            const int njt = jt + TILE;
            const int rem1 = min(TILE, jcount - njt);
            const int lim = rem1 * 12;
            const float4* s4 = gsrc + (size_t)njt * 12;
            pf0 = (tid       < lim) ? s4[tid]       : z4;
            pf1 = (tid + 256 < lim) ? s4[tid + 256] : z4;
            pf2 = (tid + 512 < lim) ? s4[tid + 512] : z4;
            if (tid < TILE) pfs = (tid < rem1) ? g_sq[jbase + njt + tid] : INF;
        }

        const int rem = min(TILE, jcount - jt);

#define PROCESS(RR)                                                          \
        {                                                                    \
            const int _r = (RR);                                             \
            const ulonglong2* xj = (const ulonglong2*)(stile + _r * 48);     \
            u64 a0 = 0, a1 = 0;                                              \
            _Pragma("unroll")                                                \
            for (int c = 0; c < 12; c += 2) {                                \
                ulonglong2 v0 = xj[c];                                       \
                ulonglong2 v1 = xj[c + 1];                                   \
                a0 = fma2(xi2[2 * c],     v0.x, a0);                         \
                a1 = fma2(xi2[2 * c + 1], v0.y, a1);                         \
                a0 = fma2(xi2[2 * c + 2], v1.x, a0);                         \
                a1 = fma2(xi2[2 * c + 3], v1.y, a1);                         \
            }                                                                \
            u64 s = add2(a0, a1);                                            \
            float lo, hi; unpack2(s, lo, hi);                                \
            float dist = fmaf(lo + hi, -2.0f, sqi + ssq[_r]);                \
            if (dist < d9[8]) {                                              \
                d9[8] = dist; n9[8] = jbase + jt + _r;                       \
                _Pragma("unroll")                                            \
                for (int k = 8; k > 0; k--) {                                \
                    if (d9[k] < d9[k - 1]) {                                 \
                        float td = d9[k]; d9[k] = d9[k - 1]; d9[k - 1] = td; \
                        int   ti = n9[k]; n9[k] = n9[k - 1]; n9[k - 1] = ti; \
                    }                                                        \
                }                                                            \
            }                                                                \
        }

        if (rem == TILE) {
#pragma unroll
            for (int u = 0; u < TILE / 4; u++) PROCESS(part + u * 4)
        } else {
            for (int rr = part; rr < rem; rr += 4) PROCESS(rr)
        }
#undef PROCESS
        // next iteration's top-of-loop sync guards the stile overwrite
    }

    // publish partials
    {
        const int base = (il * 4 + part) * KNN;
#pragma unroll
        for (int k = 0; k < KNN; k++) { smd[base + k] = d9[k]; smi[base + k] = n9[k]; }
    }
    __syncthreads();

    // 4-way lexicographic merge by (dist, idx), done by part-0 threads
    if (part == 0) {
        if (i == NNODE - 1) {
            // node 16383: alone in batch 4 -> self + 8 lowest-index -inf ties (0..7)
            g_nbr[i * KNN + 0] = NNODE - 1;
#pragma unroll
            for (int k = 1; k < KNN; k++) g_nbr[i * KNN + k] = k - 1;
        } else {
            int p[4] = {0, 0, 0, 0};
            for (int k = 0; k < KNN; k++) {
                float bd = 3.402823466e+38f; int bi = 0x7fffffff; int bq = 0;
#pragma unroll
                for (int q = 0; q < 4; q++) {
                    const int pq = p[q];
                    float dq = 3.402823466e+38f; int iq = 0x7fffffff;
                    if (pq < KNN) {
                        dq = smd[(il * 4 + q) * KNN + pq];
                        iq = smi[(il * 4 + q) * KNN + pq];
                    }
                    if (dq < bd || (dq == bd && iq < bi)) { bd = dq; bi = iq; bq = q; }
                }
                p[bq]++;
                g_nbr[i * KNN + k] = bi;
            }
        }
    }
}

// ============ kernel 3: degree over src ============
__global__ __launch_bounds__(256) void deg_kernel() {
    int e = blockIdx.x * 256 + threadIdx.x;
    if (e < NNODE * KNN) atomicAdd(&g_deg[g_nbr[e]], 1);
}

// ============ kernel 4: fused gather + (xf@W0 + tx1@W1 + b) + relu ============
// block = 384 threads = 8 rows x 48 output cols
__global__ __launch_bounds__(384) void out_kernel(const float* __restrict__ W0,
                                                  const float* __restrict__ W1,
                                                  const float* __restrict__ b,
                                                  float* __restrict__ out) {
    __shared__ float W0s[2304], W1s[2304], bs[48];
    __shared__ float sx[8][48], sg[8][48], sdin[8];
    const int tid = threadIdx.x;
    for (int k = tid; k < 2304; k += 384) { W0s[k] = W0[k]; W1s[k] = W1[k]; }
    if (tid < 48) bs[tid] = b[tid];

    const int row = tid / 48, o = tid % 48;
    const int i = blockIdx.x * 8 + row;

    sx[row][o] = g_xf[(size_t)i * 48 + o];
    float g = 0.f;
    const int* nb = &g_nbr[i * KNN];
#pragma unroll
    for (int k = 0; k < KNN; k++) {
        const int j = nb[k];
        const float dj = rsqrtf((float)g_deg[j]);
        g += dj * g_xf[(size_t)j * 48 + o];
    }
    sg[row][o] = g;
    if (o == 0) sdin[row] = rsqrtf((float)g_deg[i]);
    __syncthreads();

    float a0 = 0.f, a1 = 0.f;
#pragma unroll
    for (int c = 0; c < 48; c++) {
        a0 += sx[row][c] * W0s[c * 48 + o];
        a1 += sg[row][c] * W1s[c * 48 + o];
    }
    const float v = bs[o] + a0 - sdin[row] * a1;
    out[(size_t)i * 48 + o] = fmaxf(v, 0.f);
}

// ============ launch ============
extern "C" void kernel_launch(void* const* d_in, const int* in_sizes, int n_in,
                              void* d_out, int out_size) {
    const float* x  = (const float*)d_in[0];
    const float* W0 = (const float*)d_in[1];
    const float* W1 = (const float*)d_in[2];
    const float* b  = (const float*)d_in[3];
    float* out = (float*)d_out;

    transpose_kernel<<<256, 192>>>(x);
    knn_kernel<<<256, 256>>>();
    deg_kernel<<<(NNODE * KNN + 255) / 256, 256>>>();
    out_kernel<<<NNODE / 8, 384>>>(W0, W1, b, out);
}

// round 6
// speedup vs baseline: 1.2311x; 1.0291x over previous
#include <cuda_runtime.h>
#include <cuda_bf16.h>
#include <cstdint>

// Problem constants
#define NNODE   16384
#define CDIM    48
#define KNN     9
#define BATCHSZ 4096
#define TILE    64

typedef unsigned long long u64;
typedef unsigned int u32;

// -------- scratch (device globals; no allocation allowed) --------
__device__ __align__(256) float g_xf[NNODE * CDIM];   // [N,48] node features
__device__ float g_sq[NNODE];                         // row squared norms
__device__ int   g_nbr[NNODE * KNN];                  // knn indices
__device__ int   g_deg[NNODE];                        // degree over src
__device__ float g_dinv[NNODE];                       // rsqrt(deg)

// packed fp32x2 ops (sm_103a): 2 IEEE fp32 ops per instruction
__device__ __forceinline__ u64 fma2(u64 a, u64 b, u64 c) {
    u64 d;
    asm("fma.rn.f32x2 %0, %1, %2, %3;" : "=l"(d) : "l"(a), "l"(b), "l"(c));
    return d;
}
__device__ __forceinline__ u64 add2(u64 a, u64 b) {
    u64 d;
    asm("add.rn.f32x2 %0, %1, %2;" : "=l"(d) : "l"(a), "l"(b));
    return d;
}
__device__ __forceinline__ void unpack2(u64 v, float& lo, float& hi) {
    asm("mov.b64 {%0, %1}, %2;" : "=f"(lo), "=f"(hi) : "l"(v));
}
__device__ __forceinline__ void cp16(u32 dst_smem, const void* src) {
    asm volatile("cp.async.ca.shared.global [%0], [%1], 16;" :: "r"(dst_smem), "l"(src));
}

// ============ kernel 1: [B,C,H,W] -> [N,C] transpose + row norms + deg=0 ============
__global__ __launch_bounds__(192) void transpose_kernel(const float* __restrict__ x) {
    int bh = blockIdx.x;            // b*64 + h, 256 blocks
    __shared__ float s[48][65];
    const float* src = x + (size_t)(bh >> 6) * 48 * 4096 + (bh & 63) * 64;
    for (int idx = threadIdx.x; idx < 48 * 64; idx += 192) {
        int c = idx >> 6, w = idx & 63;
        s[c][w] = src[c * 4096 + w];
    }
    __syncthreads();
    float* dst = g_xf + (size_t)bh * 64 * 48;
    for (int idx = threadIdx.x; idx < 48 * 64; idx += 192) {
        int w = idx / 48, c = idx - w * 48;
        dst[w * 48 + c] = s[c][w];
    }
    if (threadIdx.x < 64) {
        int w = threadIdx.x;
        float acc = 0.f;
#pragma unroll
        for (int c = 0; c < 48; c++) acc += s[c][w] * s[c][w];
        g_sq[bh * 64 + w] = acc;
        g_deg[bh * 64 + w] = 0;
    }
}

// ============ kernel 2: knn (top-9 smallest dist, lower-index ties) ============
// 256 blocks x 128 threads. Block owns 64 centers; 2 threads per center split
// the candidate sweep. Candidate tiles (64 rows) double-buffered via cp.async.
// Warp lanes = 32 different centers reading the same candidate row: broadcast LDS.
__global__ __launch_bounds__(128, 4) void knn_kernel() {
    __shared__ __align__(16) float stile[2][TILE * 48];  // 2 x 12.3KB
    __shared__ float ssq[2][TILE];
    __shared__ float smd[64 * 2 * KNN];                  // partial dists (merge)
    __shared__ int   smi[64 * 2 * KNN];                  // partial idxs  (merge)

    const int tid  = threadIdx.x;
    const int il   = tid & 63;
    const int part = tid >> 6;                            // 0 or 1
    const int i    = blockIdx.x * 64 + il;
    const int batch  = blockIdx.x >> 6;
    const int jbase  = batch << 12;
    const int jcount = (batch == 3) ? (BATCHSZ - 1) : BATCHSZ;  // exclude node 16383

    const u32 stile_a = (u32)__cvta_generic_to_shared(&stile[0][0]);

    // center features in registers (as fp32x2 pairs)
    u64 xi2[24];
    {
        const ulonglong2* xr = (const ulonglong2*)(g_xf + (size_t)i * CDIM);
#pragma unroll
        for (int c = 0; c < 12; c++) {
            ulonglong2 v = xr[c];
            xi2[2 * c] = v.x; xi2[2 * c + 1] = v.y;
        }
    }
    const float sqi = g_sq[i];
    const float INF = __int_as_float(0x7f800000);

    float d9[KNN]; int n9[KNN];
#pragma unroll
    for (int k = 0; k < KNN; k++) { d9[k] = 3.402823466e+38f; n9[k] = 0x7fffffff; }

    const float4* gsrc = (const float4*)(g_xf + (size_t)jbase * CDIM);

    // preload tile 0 (rows are always valid memory; ssq padded with INF)
    {
#pragma unroll
        for (int q = 0; q < 6; q++) {
            const int idx = tid + q * 128;                // float4 index 0..767
            cp16(stile_a + idx * 16, gsrc + idx);
        }
        asm volatile("cp.async.commit_group;");
        if (tid < TILE) ssq[0][tid] = g_sq[jbase + tid];  // tile0 rows always < jcount
    }

    const int ntiles = BATCHSZ / TILE;  // 64
    for (int t = 0; t < ntiles; t++) {
        __syncthreads();   // all threads done computing tile t-1 (buffers free)
        if (t + 1 < ntiles) {
            const int nb = (t + 1) & 1;
            const float4* s4 = gsrc + (size_t)(t + 1) * TILE * 12;
#pragma unroll
            for (int q = 0; q < 6; q++) {
                const int idx = tid + q * 128;
                cp16(stile_a + (nb * TILE * 48) * 4 + idx * 16, s4 + idx);
            }
            asm volatile("cp.async.commit_group;");
            if (tid < TILE) {
                const int jn = (t + 1) * TILE + tid;
                ssq[nb][tid] = (jn < jcount) ? g_sq[jbase + jn] : INF;
            }
            asm volatile("cp.async.wait_group 1;");
        } else {
            asm volatile("cp.async.wait_group 0;");
        }
        __syncthreads();   // tile t fully visible to everyone

        const int jt = t * TILE;
        const float* buf = &stile[t & 1][0];
        const float* sbq = &ssq[t & 1][0];

#define PROCESS(SS)                                                              \
        {                                                                        \
            const int _r = part + 2 * (SS);                                      \
            const ulonglong2* _xj = (const ulonglong2*)(buf + _r * 48);          \
            u64 _a0 = 0, _a1 = 0;                                                \
            _Pragma("unroll")                                                    \
            for (int _c = 0; _c < 12; _c += 2) {                                 \
                ulonglong2 _v0 = _xj[_c];                                        \
                ulonglong2 _v1 = _xj[_c + 1];                                    \
                _a0 = fma2(xi2[2 * _c],     _v0.x, _a0);                         \
                _a1 = fma2(xi2[2 * _c + 1], _v0.y, _a1);                         \
                _a0 = fma2(xi2[2 * _c + 2], _v1.x, _a0);                         \
                _a1 = fma2(xi2[2 * _c + 3], _v1.y, _a1);                         \
            }                                                                    \
            u64 _sum = add2(_a0, _a1);                                           \
            float _lo, _hi; unpack2(_sum, _lo, _hi);                             \
            float _dist = fmaf(_lo + _hi, -2.0f, sqi + sbq[_r]);                 \
            if (_dist < d9[8]) {                                                 \
                d9[8] = _dist; n9[8] = jbase + jt + _r;                          \
                _Pragma("unroll")                                                \
                for (int _k = 8; _k > 0; _k--) {                                 \
                    if (d9[_k] < d9[_k - 1]) {                                   \
                        float _td = d9[_k]; d9[_k] = d9[_k - 1]; d9[_k - 1] = _td; \
                        int   _ti = n9[_k]; n9[_k] = n9[_k - 1]; n9[_k - 1] = _ti; \
                    }                                                            \
                }                                                                \
            }                                                                    \
        }

#pragma unroll 8
        for (int ss = 0; ss < TILE / 2; ss++) PROCESS(ss)
#undef PROCESS
    }

    // publish partials
    {
        const int base = (il * 2 + part) * KNN;
#pragma unroll
        for (int k = 0; k < KNN; k++) { smd[base + k] = d9[k]; smi[base + k] = n9[k]; }
    }
    __syncthreads();

    // 2-way lexicographic merge by (dist, idx), done by part-0 threads
    if (part == 0) {
        if (i == NNODE - 1) {
            // node 16383: alone in batch 4 -> self + 8 lowest-index -inf ties (0..7)
            g_nbr[i * KNN + 0] = NNODE - 1;
#pragma unroll
            for (int k = 1; k < KNN; k++) g_nbr[i * KNN + k] = k - 1;
        } else {
            int p[2] = {0, 0};
            for (int k = 0; k < KNN; k++) {
                float bd = 3.402823466e+38f; int bi = 0x7fffffff; int bq = 0;
#pragma unroll
                for (int q = 0; q < 2; q++) {
                    const int pq = p[q];
                    float dq = 3.402823466e+38f; int iq = 0x7fffffff;
                    if (pq < KNN) {
                        dq = smd[(il * 2 + q) * KNN + pq];
                        iq = smi[(il * 2 + q) * KNN + pq];
                    }
                    if (dq < bd || (dq == bd && iq < bi)) { bd = dq; bi = iq; bq = q; }
                }
                p[bq]++;
                g_nbr[i * KNN + k] = bi;
            }
        }
    }
}

// ============ kernel 3: degree over src ============
__global__ __launch_bounds__(256) void deg_kernel() {
    int e = blockIdx.x * 256 + threadIdx.x;
    if (e < NNODE * KNN) atomicAdd(&g_deg[g_nbr[e]], 1);
}

// ============ kernel 3b: dinv = rsqrt(deg) ============
__global__ __launch_bounds__(256) void dinv_kernel() {
    int i = blockIdx.x * 256 + threadIdx.x;
    if (i < NNODE) g_dinv[i] = rsqrtf((float)g_deg[i]);
}

// ============ kernel 4: fused gather + (xf@W0 + tx1@W1 + b) + relu ============
// block = 384 threads = 8 rows x 48 output cols
__global__ __launch_bounds__(384) void out_kernel(const float* __restrict__ W0,
                                                  const float* __restrict__ W1,
                                                  const float* __restrict__ b,
                                                  float* __restrict__ out) {
    __shared__ float W0s[2304], W1s[2304], bs[48];
    __shared__ float sx[8][48], sg[8][48], sdin[8];
    const int tid = threadIdx.x;
    for (int k = tid; k < 2304; k += 384) { W0s[k] = W0[k]; W1s[k] = W1[k]; }
    if (tid < 48) bs[tid] = b[tid];

    const int row = tid / 48, o = tid % 48;
    const int i = blockIdx.x * 8 + row;

    sx[row][o] = g_xf[(size_t)i * 48 + o];
    float g = 0.f;
    const int* nb = &g_nbr[i * KNN];
#pragma unroll
    for (int k = 0; k < KNN; k++) {
        const int j = nb[k];
        g += g_dinv[j] * g_xf[(size_t)j * 48 + o];
    }
    sg[row][o] = g;
    if (o == 0) sdin[row] = g_dinv[i];
    __syncthreads();

    float a0 = 0.f, a1 = 0.f;
#pragma unroll
    for (int c = 0; c < 48; c++) {
        a0 += sx[row][c] * W0s[c * 48 + o];
        a1 += sg[row][c] * W1s[c * 48 + o];
    }
    const float v = bs[o] + a0 - sdin[row] * a1;
    out[(size_t)i * 48 + o] = fmaxf(v, 0.f);
}

// ============ launch ============
extern "C" void kernel_launch(void* const* d_in, const int* in_sizes, int n_in,
                              void* d_out, int out_size) {
    const float* x  = (const float*)d_in[0];
    const float* W0 = (const float*)d_in[1];
    const float* W1 = (const float*)d_in[2];
    const float* b  = (const float*)d_in[3];
    float* out = (float*)d_out;

    transpose_kernel<<<256, 192>>>(x);
    knn_kernel<<<256, 128>>>();
    deg_kernel<<<(NNODE * KNN + 255) / 256, 256>>>();
    dinv_kernel<<<NNODE / 256, 256>>>();
    out_kernel<<<NNODE / 8, 384>>>(W0, W1, b, out);
}